// round 1
// baseline (speedup 1.0000x reference)
#include <cuda_runtime.h>
#include <cuda_bf16.h>

// Problem constants (fixed shapes from reference setup_inputs)
#define BB 8
#define CC 64
#define NN 100000
#define RR 32
#define R3 (RR * RR * RR)            // 32768
#define VOX_ELEMS (BB * CC * R3)     // 16,777,216
#define PTS (BB * NN)                // 800,000

// Scratch (no device allocation allowed -> __device__ globals)
__device__ float g_mean[BB * 3];
__device__ int   g_idx[PTS];
__device__ int   g_cnt[BB * R3];

// ---------------------------------------------------------------------------
// K0: zero the voxel-sum region of d_out and the count histogram
// ---------------------------------------------------------------------------
__global__ void zero_kernel(float4* __restrict__ vox4) {
    int i = blockIdx.x * blockDim.x + threadIdx.x;
    if (i < VOX_ELEMS / 4) {
        vox4[i] = make_float4(0.f, 0.f, 0.f, 0.f);
    }
    if (i < BB * R3) {
        g_cnt[i] = 0;
    }
}

// ---------------------------------------------------------------------------
// K1: deterministic per-(batch,dim) mean. One block per (b,d); fixed-order
// strided accumulate + shared tree reduce => identical result every launch.
// ---------------------------------------------------------------------------
__global__ void mean_kernel(const float* __restrict__ coords) {
    __shared__ float sm[1024];
    int bd = blockIdx.x;                 // 0..23
    const float* p = coords + (size_t)bd * NN;
    float s = 0.f;
    for (int i = threadIdx.x; i < NN; i += blockDim.x) s += p[i];
    sm[threadIdx.x] = s;
    __syncthreads();
    for (int off = 512; off > 0; off >>= 1) {
        if (threadIdx.x < off) sm[threadIdx.x] += sm[threadIdx.x + off];
        __syncthreads();
    }
    if (threadIdx.x == 0) g_mean[bd] = sm[0] * (1.0f / (float)NN);
}

// ---------------------------------------------------------------------------
// K2: per-point normalize, write norm_coords, compute flat voxel idx, count.
// ---------------------------------------------------------------------------
__global__ void point_kernel(const float* __restrict__ coords,
                             float* __restrict__ norm_out) {
    int t = blockIdx.x * blockDim.x + threadIdx.x;
    if (t >= PTS) return;
    int b = t / NN;
    int n = t - b * NN;

    int vc[3];
#pragma unroll
    for (int d = 0; d < 3; d++) {
        float c = coords[(size_t)(b * 3 + d) * NN + n];
        // reference: ((c - mean) + 1) / 2 * r, clip [0, r-1]
        // *0.5f and *32.f are exact power-of-two scalings -> bit-identical order
        float v = (c - g_mean[b * 3 + d] + 1.0f) * 0.5f;
        v = v * 32.0f;
        v = fminf(fmaxf(v, 0.0f), 31.0f);
        norm_out[(size_t)(b * 3 + d) * NN + n] = v;
        vc[d] = (int)rintf(v);           // round-half-to-even == jnp.round
    }
    int flat = vc[0] * (RR * RR) + vc[1] * RR + vc[2];
    g_idx[t] = flat;
    atomicAdd(&g_cnt[b * R3 + flat], 1);
}

// ---------------------------------------------------------------------------
// K3: scatter-add features into the voxel sum grid (d_out region).
// One thread per point; loops channels. For a fixed c, consecutive threads
// read consecutive n -> fully coalesced feature reads. One idx load/thread.
// ---------------------------------------------------------------------------
__global__ void scatter_kernel(const float* __restrict__ feat,
                               float* __restrict__ vox) {
    int t = blockIdx.x * blockDim.x + threadIdx.x;
    if (t >= PTS) return;
    int b = t / NN;
    int n = t - b * NN;
    int idx = g_idx[t];

    const float* f = feat + (size_t)b * CC * NN + n;
    float* vb = vox + (size_t)b * CC * R3 + idx;
#pragma unroll 8
    for (int c = 0; c < CC; c++) {
        atomicAdd(vb + c * R3, f[(size_t)c * NN]);
    }
}

// ---------------------------------------------------------------------------
// K4: divide sums by max(count,1) for all channels of each voxel.
// For a fixed c, consecutive threads touch consecutive v -> coalesced.
// ---------------------------------------------------------------------------
__global__ void finalize_kernel(float* __restrict__ vox) {
    int t = blockIdx.x * blockDim.x + threadIdx.x;
    if (t >= BB * R3) return;
    int b = t / R3;
    int v = t - b * R3;
    float cnt = (float)g_cnt[t];
    float inv = 1.0f / fmaxf(cnt, 1.0f);
    float* vb = vox + (size_t)b * CC * R3 + v;
#pragma unroll 8
    for (int c = 0; c < CC; c++) {
        vb[c * R3] *= inv;
    }
}

// ---------------------------------------------------------------------------
extern "C" void kernel_launch(void* const* d_in, const int* in_sizes, int n_in,
                              void* d_out, int out_size) {
    const float* features = (const float*)d_in[0];  // [B, C, N]
    const float* coords   = (const float*)d_in[1];  // [B, 3, N]
    float* out = (float*)d_out;
    float* vox  = out;                 // [B, C, R, R, R]
    float* norm = out + VOX_ELEMS;     // [B, 3, N]

    // K0: zero sums + counts
    {
        int tot = VOX_ELEMS / 4;       // covers BB*R3 too (262144 < 4194304)
        int threads = 256;
        int blocks = (tot + threads - 1) / threads;
        zero_kernel<<<blocks, threads>>>((float4*)vox);
    }
    // K1: deterministic means
    mean_kernel<<<BB * 3, 1024>>>(coords);
    // K2: normalize + index + histogram
    {
        int threads = 256;
        int blocks = (PTS + threads - 1) / threads;
        point_kernel<<<blocks, threads>>>(coords, norm);
    }
    // K3: scatter-add
    {
        int threads = 256;
        int blocks = (PTS + threads - 1) / threads;
        scatter_kernel<<<blocks, threads>>>(features, vox);
    }
    // K4: divide by counts
    {
        int threads = 256;
        int blocks = (BB * R3 + threads - 1) / threads;
        finalize_kernel<<<blocks, threads>>>(vox);
    }
}

// round 5
// speedup vs baseline: 2.2379x; 2.2379x over previous
#include <cuda_runtime.h>
#include <cuda_bf16.h>

// Fixed shapes from reference setup_inputs
#define BB 8
#define CC 64
#define NN 100000
#define RR 32
#define R3 (RR * RR * RR)            // 32768
#define VOX_ELEMS (BB * CC * R3)     // 16,777,216
#define PTS (BB * NN)                // 800,000

// Scratch (no device allocation allowed -> __device__ globals)
__device__ float g_voxT[(size_t)BB * R3 * CC];   // [B][R3][C] transposed accum, 67MB
__device__ float g_mean[BB * 3];
__device__ int   g_idx[PTS];
__device__ int   g_cnt[BB * R3];

// ---------------------------------------------------------------------------
// K0: zero transposed accumulator + count histogram
// ---------------------------------------------------------------------------
__global__ void zero_kernel() {
    int i = blockIdx.x * blockDim.x + threadIdx.x;
    if (i < VOX_ELEMS / 4) {
        ((float4*)g_voxT)[i] = make_float4(0.f, 0.f, 0.f, 0.f);
    }
    if (i < BB * R3) {
        g_cnt[i] = 0;
    }
}

// ---------------------------------------------------------------------------
// K1: deterministic per-(batch,dim) mean — BIT-EXACT copy of the Round-1
// algorithm (one 1024-thread block per (b,d), strided accumulate + tree).
// The summation ORDER is load-bearing: it determines the mean's low bits,
// which decide rint() voxel assignment for boundary points. Round 1 passed
// with this exact ordering; do not change it.
// ---------------------------------------------------------------------------
__global__ void mean_kernel(const float* __restrict__ coords) {
    __shared__ float sm[1024];
    int bd = blockIdx.x;                 // 0..23
    const float* p = coords + (size_t)bd * NN;
    float s = 0.f;
    for (int i = threadIdx.x; i < NN; i += blockDim.x) s += p[i];
    sm[threadIdx.x] = s;
    __syncthreads();
    for (int off = 512; off > 0; off >>= 1) {
        if (threadIdx.x < off) sm[threadIdx.x] += sm[threadIdx.x + off];
        __syncthreads();
    }
    if (threadIdx.x == 0) g_mean[bd] = sm[0] * (1.0f / (float)NN);
}

// ---------------------------------------------------------------------------
// K2: per-point normalize, write norm_coords, compute flat voxel idx, count.
// ---------------------------------------------------------------------------
__global__ void point_kernel(const float* __restrict__ coords,
                             float* __restrict__ norm_out) {
    int t = blockIdx.x * blockDim.x + threadIdx.x;
    if (t >= PTS) return;
    int b = t / NN;
    int n = t - b * NN;

    int vc[3];
#pragma unroll
    for (int d = 0; d < 3; d++) {
        float c = coords[(size_t)(b * 3 + d) * NN + n];
        // ((c - mean) + 1) / 2 * r, clip [0, r-1]; *0.5 and *32 are exact
        float v = (c - g_mean[b * 3 + d] + 1.0f) * 0.5f;
        v = v * 32.0f;
        v = fminf(fmaxf(v, 0.0f), 31.0f);
        norm_out[(size_t)(b * 3 + d) * NN + n] = v;
        vc[d] = (int)rintf(v);       // round-half-to-even == jnp.round
    }
    int flat = vc[0] * (RR * RR) + vc[1] * RR + vc[2];
    g_idx[t] = flat;
    atomicAdd(&g_cnt[b * R3 + flat], 1);
}

// ---------------------------------------------------------------------------
// K3: scatter-add features into transposed accumulator with v4 reductions.
// One thread per point; 16x red.global.add.v4.f32 (4x fewer L2 atomic
// transactions than 64 scalar REDs). Feature loads coalesced across warp.
// ---------------------------------------------------------------------------
__global__ void scatter_kernel(const float* __restrict__ feat) {
    int t = blockIdx.x * blockDim.x + threadIdx.x;
    if (t >= PTS) return;
    int b = t / NN;
    int n = t - b * NN;
    int idx = g_idx[t];

    const float* f = feat + (size_t)b * CC * NN + n;
    float* dst = g_voxT + ((size_t)b * R3 + idx) * CC;   // 256B-aligned (C=64)

#pragma unroll
    for (int cq = 0; cq < CC / 4; cq++) {
        float v0 = f[(size_t)(4 * cq + 0) * NN];
        float v1 = f[(size_t)(4 * cq + 1) * NN];
        float v2 = f[(size_t)(4 * cq + 2) * NN];
        float v3 = f[(size_t)(4 * cq + 3) * NN];
        asm volatile(
            "red.global.add.v4.f32 [%0], {%1, %2, %3, %4};"
            :: "l"(dst + 4 * cq), "f"(v0), "f"(v1), "f"(v2), "f"(v3)
            : "memory");
    }
}

// ---------------------------------------------------------------------------
// K4: tiled transpose [B][R3][C] -> [B][C][R3] with divide-by-count.
// Tile = 32 voxels x 64 channels. Block: 256 threads = (64, 4).
// ---------------------------------------------------------------------------
__global__ void transpose_kernel(float* __restrict__ vox) {
    __shared__ float tile[32][65];   // [v][c], pad to kill bank conflicts
    __shared__ float sinv[32];

    int blk = blockIdx.x;            // b * (R3/32) + vtile
    int b = blk / (R3 / 32);
    int v0 = (blk - b * (R3 / 32)) * 32;

    int tx = threadIdx.x;            // 0..63 = channel
    int ty = threadIdx.y;            // 0..3

    int lin = ty * 64 + tx;          // 0..255
    if (lin < 32) {
        float cnt = (float)g_cnt[b * R3 + v0 + lin];
        sinv[lin] = 1.0f / fmaxf(cnt, 1.0f);
    }

    // load: rows of 64 consecutive floats -> coalesced
    const float* src = g_voxT + ((size_t)b * R3 + v0) * CC;
#pragma unroll
    for (int vv = 0; vv < 32; vv += 4) {
        int v = vv + ty;
        tile[v][tx] = src[(size_t)v * CC + tx];
    }
    __syncthreads();

    // store: for each channel row, 32 consecutive voxels -> coalesced 128B
    float* dstb = vox + (size_t)b * CC * R3 + v0;
#pragma unroll
    for (int j = 0; j < 8; j++) {
        int elem = j * 256 + lin;    // 0..2047
        int c = elem >> 5;           // 0..63
        int v = elem & 31;           // 0..31
        dstb[(size_t)c * R3 + v] = tile[v][c] * sinv[v];
    }
}

// ---------------------------------------------------------------------------
extern "C" void kernel_launch(void* const* d_in, const int* in_sizes, int n_in,
                              void* d_out, int out_size) {
    const float* features = (const float*)d_in[0];  // [B, C, N]
    const float* coords   = (const float*)d_in[1];  // [B, 3, N]
    float* out = (float*)d_out;
    float* vox  = out;                 // [B, C, R, R, R]
    float* norm = out + VOX_ELEMS;     // [B, 3, N]

    // K0: zero scratch accumulator + counts
    {
        int tot = VOX_ELEMS / 4;
        zero_kernel<<<(tot + 255) / 256, 256>>>();
    }
    // K1: deterministic mean (Round-1 bit-exact ordering)
    mean_kernel<<<BB * 3, 1024>>>(coords);
    // K2: normalize + index + histogram
    point_kernel<<<(PTS + 255) / 256, 256>>>(coords, norm);
    // K3: v4 scatter-add into transposed scratch
    scatter_kernel<<<(PTS + 255) / 256, 256>>>(features);
    // K4: transpose + divide into d_out
    transpose_kernel<<<BB * (R3 / 32), dim3(64, 4)>>>(vox);
}